// round 12
// baseline (speedup 1.0000x reference)
#include <cuda_runtime.h>
#include <math.h>
#include <stdint.h>

// ---------------- problem constants ----------------
#define T_P 400
#define T_Q 30
#define NB  32
#define NE  300
#define NH  300
#define NF  300
#define NA  30
#define MP  (T_P*NB)   // 12800 rows (t*32+b)
#define MQ  (T_Q*NB)   // 960

// GRU cluster layout
#define CPC   8        // CTAs per cluster
#define UPC   40       // units per CTA (8*40=320 >= 300, tail zero-padded)
#define BPG   4        // batches per cluster(group)
#define HROW  320      // padded h/k row length (8 kq * 40)
#define KSL   40       // k slice per lane
#define GRU_WARPS 10   // 4 units per warp
#define GRU_THREADS 320
#define WS_FLOATS (120 * HROW)            // 38400
#define HS_FLOATS (2 * BPG * HROW)        // 2560
#define GRU_SMEM_BYTES ((WS_FLOATS + HS_FLOATS) * 4)   // 163840

// ---------------- scratch layout (floats) ----------------
#define OFF_PSTAR 0L                      // [MP][600]  (p_emb | q_align)
#define OFF_QEMB  7680000L                // [MQ][300]
#define OFF_FFP   7968000L                // [MP][300]
#define OFF_FFQ   11808000L               // [MQ][300]
#define OFF_XP    12096000L               // [2][MP][900]
#define OFF_H1    35136000L               // [MP][600]
#define OFF_H2    42816000L               // [MP][600]
#define OFF_STT   50496000L               // [MP][300]
#define OFF_END   54336000L               // [MP][300]
#define OFF_FIN   58176000L               // [NB][12000]
#define SCRATCH_TOTAL 58560000L

__device__ float g_scratch[SCRATCH_TOTAL];

// ---------------- packed f32x2 helpers (FFMA2 path) ----------------
__device__ __forceinline__ unsigned long long fma2(unsigned long long a,
                                                   unsigned long long b,
                                                   unsigned long long c) {
    unsigned long long d;
    asm("fma.rn.f32x2 %0, %1, %2, %3;" : "=l"(d) : "l"(a), "l"(b), "l"(c));
    return d;
}
__device__ __forceinline__ unsigned long long pack2(float lo, float hi) {
    unsigned long long r;
    asm("mov.b64 %0, {%1, %2};" : "=l"(r) : "f"(lo), "f"(hi));
    return r;
}
__device__ __forceinline__ float2 unpack2(unsigned long long v) {
    float2 f;
    asm("mov.b64 {%0, %1}, %2;" : "=f"(f.x), "=f"(f.y) : "l"(v));
    return f;
}

// ---------------- cluster helpers ----------------
__device__ __forceinline__ uint32_t smem_u32(const void* p) {
    uint32_t a;
    asm("{ .reg .u64 t; cvta.to.shared.u64 t, %1; cvt.u32.u64 %0, t; }"
        : "=r"(a) : "l"(p));
    return a;
}
__device__ __forceinline__ uint32_t my_cluster_rank() {
    uint32_t r;
    asm("mov.u32 %0, %%cluster_ctarank;" : "=r"(r));
    return r;
}
__device__ __forceinline__ uint32_t mapa_u32(uint32_t local_addr, uint32_t rank) {
    uint32_t r;
    asm("mapa.shared::cluster.u32 %0, %1, %2;" : "=r"(r) : "r"(local_addr), "r"(rank));
    return r;
}
__device__ __forceinline__ void st_cluster_b64(uint32_t addr, unsigned long long v) {
    asm volatile("st.shared::cluster.b64 [%0], %1;" :: "r"(addr), "l"(v) : "memory");
}
__device__ __forceinline__ void cluster_sync() {
    asm volatile("barrier.cluster.arrive.aligned;" ::: "memory");
    asm volatile("barrier.cluster.wait.aligned;" ::: "memory");
}

// ---------------- embedding gather ----------------
__global__ void gather_kernel(const int* __restrict__ tok,
                              const float* __restrict__ embed,
                              float* __restrict__ dst, int rows, int dstride) {
    long idx = (long)blockIdx.x * blockDim.x + threadIdx.x;
    long tot = (long)rows * NE;
    if (idx >= tot) return;
    int m = (int)(idx / NE), e = (int)(idx % NE);
    dst[(long)m * dstride + e] = embed[(long)tok[m] * NE + e];
}

// ---------------- SGEMM (f32x2): C[M,N] = A[M,K](lda) @ W[N,K]^T + bias ----------------
#define BM 128
#define BN 128
#define BK 16
__global__ __launch_bounds__(256, 2)
void sgemm_kernel(int M, int N, int K,
                  const float* __restrict__ A, int lda,
                  const float* __restrict__ W,
                  const float* __restrict__ bias,
                  float* __restrict__ C, int ldc, int do_relu) {
    __shared__ float As[BK][BM + 4];
    __shared__ float Bs[BK][BN + 4];
    int tid  = threadIdx.x;
    int trow = tid >> 4;          // 0..15 (M dir)
    int tcol = tid & 15;          // 0..15 (N dir)
    int aRow = tid >> 2;          // 0..63
    int aCol = tid & 3;           // 0..3 (float4 along K)
    int mBase = blockIdx.y * BM;
    int nBase = blockIdx.x * BN;

    unsigned long long accP[4][8];   // pairs over M: (i, i+1) x 8 N
#pragma unroll
    for (int i = 0; i < 4; i++)
#pragma unroll
        for (int j = 0; j < 8; j++) accP[i][j] = 0ULL;

    for (int k0 = 0; k0 < K; k0 += BK) {
#pragma unroll
        for (int r = 0; r < 2; r++) {
            int m = mBase + aRow + r * 64;
            int k = k0 + aCol * 4;
            float4 v = make_float4(0.f, 0.f, 0.f, 0.f);
            if (m < M && k < K)
                v = *reinterpret_cast<const float4*>(A + (long)m * lda + k);
            As[aCol * 4 + 0][aRow + r * 64] = v.x;
            As[aCol * 4 + 1][aRow + r * 64] = v.y;
            As[aCol * 4 + 2][aRow + r * 64] = v.z;
            As[aCol * 4 + 3][aRow + r * 64] = v.w;
        }
#pragma unroll
        for (int r = 0; r < 2; r++) {
            int n = nBase + aRow + r * 64;
            int k = k0 + aCol * 4;
            float4 v = make_float4(0.f, 0.f, 0.f, 0.f);
            if (n < N && k < K)
                v = *reinterpret_cast<const float4*>(W + (long)n * K + k);
            Bs[aCol * 4 + 0][aRow + r * 64] = v.x;
            Bs[aCol * 4 + 1][aRow + r * 64] = v.y;
            Bs[aCol * 4 + 2][aRow + r * 64] = v.z;
            Bs[aCol * 4 + 3][aRow + r * 64] = v.w;
        }
        __syncthreads();
#pragma unroll
        for (int kk = 0; kk < BK; kk++) {
            ulonglong2 rm01 = *reinterpret_cast<const ulonglong2*>(&As[kk][trow * 8]);
            ulonglong2 rm23 = *reinterpret_cast<const ulonglong2*>(&As[kk][trow * 8 + 4]);
            float4 rnA = *reinterpret_cast<const float4*>(&Bs[kk][tcol * 8]);
            float4 rnB = *reinterpret_cast<const float4*>(&Bs[kk][tcol * 8 + 4]);
            unsigned long long rnD[8];
            rnD[0] = pack2(rnA.x, rnA.x); rnD[1] = pack2(rnA.y, rnA.y);
            rnD[2] = pack2(rnA.z, rnA.z); rnD[3] = pack2(rnA.w, rnA.w);
            rnD[4] = pack2(rnB.x, rnB.x); rnD[5] = pack2(rnB.y, rnB.y);
            rnD[6] = pack2(rnB.z, rnB.z); rnD[7] = pack2(rnB.w, rnB.w);
            unsigned long long rmP[4] = { rm01.x, rm01.y, rm23.x, rm23.y };
#pragma unroll
            for (int i = 0; i < 4; i++)
#pragma unroll
                for (int j = 0; j < 8; j++)
                    accP[i][j] = fma2(rmP[i], rnD[j], accP[i][j]);
        }
        __syncthreads();
    }
#pragma unroll
    for (int i2 = 0; i2 < 4; i2++) {
#pragma unroll
        for (int j = 0; j < 8; j++) {
            int n = nBase + tcol * 8 + j;
            if (n >= N) continue;
            float2 v2 = unpack2(accP[i2][j]);
            float bsv = bias[n];
            int m0 = mBase + trow * 8 + 2 * i2;
            float v = v2.x + bsv;
            if (do_relu) v = fmaxf(v, 0.0f);
            if (m0 < M) C[(long)m0 * ldc + n] = v;
            v = v2.y + bsv;
            if (do_relu) v = fmaxf(v, 0.0f);
            if (m0 + 1 < M) C[(long)(m0 + 1) * ldc + n] = v;
        }
    }
}

// ---------------- attention: scores -> softmax -> q_align (warp per (p,b)) ----------------
__global__ void attn_kernel(const float* __restrict__ ffp,
                            const float* __restrict__ ffq,
                            const float* __restrict__ qemb,
                            float* __restrict__ pstar,
                            const float* __restrict__ pmask,
                            const float* __restrict__ qmask) {
    int gw = (blockIdx.x * blockDim.x + threadIdx.x) >> 5;
    int lane = threadIdx.x & 31;
    if (gw >= MP) return;
    int b = gw & 31;
    int m = gw;

    float fp[10];
#pragma unroll
    for (int c = 0; c < 10; c++) {
        int f = lane + 32 * c;
        fp[c] = (f < NF) ? ffp[(long)m * NF + f] : 0.0f;
    }
    float pm = pmask[m];

    float myscore = 0.0f;
    for (int q = 0; q < T_Q; q++) {
        const float* fq = ffq + (long)(q * NB + b) * NF;
        float a = 0.0f;
#pragma unroll
        for (int c = 0; c < 10; c++) {
            int f = lane + 32 * c;
            if (f < NF) a += fp[c] * fq[f];
        }
#pragma unroll
        for (int o = 16; o; o >>= 1) a += __shfl_xor_sync(0xffffffffu, a, o);
        float s = a * pm * qmask[q * NB + b];
        if (lane == q) myscore = s;
    }
    float val = (lane < T_Q) ? myscore : -INFINITY;
    float mx = val;
#pragma unroll
    for (int o = 16; o; o >>= 1) mx = fmaxf(mx, __shfl_xor_sync(0xffffffffu, mx, o));
    float e = (lane < T_Q) ? expf(val - mx) : 0.0f;
    float sum = e;
#pragma unroll
    for (int o = 16; o; o >>= 1) sum += __shfl_xor_sync(0xffffffffu, sum, o);
    float w = e / sum;

    float acc[10];
#pragma unroll
    for (int c = 0; c < 10; c++) acc[c] = 0.0f;
    for (int q = 0; q < T_Q; q++) {
        float wq = __shfl_sync(0xffffffffu, w, q);
        const float* qe = qemb + (long)(q * NB + b) * NE;
#pragma unroll
        for (int c = 0; c < 10; c++) {
            int f = lane + 32 * c;
            if (f < NE) acc[c] += wq * qe[f];
        }
    }
#pragma unroll
    for (int c = 0; c < 10; c++) {
        int f = lane + 32 * c;
        if (f < NE) pstar[(long)m * 600 + 300 + f] = acc[c];
    }
}

// ---------------- persistent bi-GRU layer (cluster + DSMEM exchange) ----------------
// grid = 128 CTAs, __cluster_dims__(8): 16 clusters = (dir 0..1) x (bgroup 0..7, 4 batches).
// CTA rank r owns units [40r, 40r+40) (tail >=300 zero-padded). 320 threads = 10 warps,
// warp w owns 4 units (12 gate rows). Lanes: lb = lane&3 -> batch, kq = lane>>2 -> 40-wide
// k slice. h lives in a double-buffered smem tile [2][4][320]; producers push new h into
// all 8 peer CTAs via st.shared::cluster; one barrier.cluster per step.
__global__ __launch_bounds__(GRU_THREADS, 1) __cluster_dims__(CPC, 1, 1)
void gru_kernel(const float* __restrict__ whh,     // [2][900][300] for this layer
                const float* __restrict__ bhh,     // [2][900]
                const float* __restrict__ xp_all,  // [2][MP][900] (x@Wih^T + b_ih)
                float* __restrict__ out) {         // [MP][600]
    extern __shared__ float sm[];
    float* ws   = sm;              // [120][HROW] row rr = ul*3 + gate
    float* h_sm = sm + WS_FLOATS;  // [2][BPG][HROW]

    int grp = blockIdx.x >> 3;        // 0..15
    int dir = grp >> 3;               // 0..1
    int bg  = grp & 7;                // 0..7 (4 batches each)
    uint32_t rank = my_cluster_rank();
    int cu0 = (int)rank * UPC;        // first global unit owned by this CTA
    int tid = threadIdx.x;
    int wid = tid >> 5, lane = tid & 31;
    int lb = lane & 3, kq = lane >> 2;

    // ---- stage this CTA's 120 weight rows (unit-major, gate-minor), zero-padded ----
    const float* wbase = whh + (long)dir * 900 * 300;
    for (int e = tid; e < 120 * HROW; e += GRU_THREADS) {
        int rr = e / HROW, k = e % HROW;
        int ul = rr / 3, gate = rr % 3;
        int gu = cu0 + ul;
        float v = 0.0f;
        if (gu < 300 && k < 300) v = wbase[(long)(gate * 300 + gu) * 300 + k];
        ws[e] = v;
    }
    // ---- zero both h buffers ----
    for (int e = tid; e < HS_FLOATS; e += GRU_THREADS) h_sm[e] = 0.0f;

    // ---- precompute per-rank DSMEM base addresses of h_sm (both buffers) ----
    uint32_t h_local = smem_u32(h_sm);
    uint32_t peer_base[CPC];
#pragma unroll
    for (int r = 0; r < CPC; r++) peer_base[r] = mapa_u32(h_local, (uint32_t)r);

    int gbase = cu0 + 4 * wid;            // first unit of this warp (multiple of 4)
    bool valid_units = (gbase < 300);     // all 4 valid iff true (300 % 4 == 0)
    int bglob = bg * BPG + lb;
    const float* bh = bhh + (long)dir * 900;
    float4 br4, bz4, bn4;
    if (lane < 4 && valid_units) {
        br4 = *reinterpret_cast<const float4*>(bh + gbase);
        bz4 = *reinterpret_cast<const float4*>(bh + 300 + gbase);
        bn4 = *reinterpret_cast<const float4*>(bh + 600 + gbase);
    }

    __syncthreads();
    cluster_sync();   // all CTAs initialized before any peer writes

    for (int step = 0; step < T_P; step++) {
        int cur = step & 1;
        int nxt = cur ^ 1;
        int tt  = dir ? (T_P - 1 - step) : step;

        // ---- prefetch xp gate inputs (producers only; hidden behind dot) ----
        float4 xr4, xz4, xn4, hold4;
        if (lane < 4 && valid_units) {
            const float* xp = xp_all + ((long)dir * MP + (long)tt * NB + bglob) * 900;
            xr4 = *reinterpret_cast<const float4*>(xp + gbase);
            xz4 = *reinterpret_cast<const float4*>(xp + 300 + gbase);
            xn4 = *reinterpret_cast<const float4*>(xp + 600 + gbase);
            hold4 = *reinterpret_cast<const float4*>(&h_sm[(cur * BPG + lb) * HROW + gbase]);
        }

        // ---- load my h slice (40 floats = 10 x LDS.128) ----
        ulonglong2 hPP[10];
        {
            const ulonglong2* hrow = reinterpret_cast<const ulonglong2*>(
                &h_sm[(cur * BPG + lb) * HROW + kq * KSL]);
#pragma unroll
            for (int i = 0; i < 10; i++) hPP[i] = hrow[i];
        }

        // ---- dot: 12 rows (4 units x 3 gates), f32x2 dual-chain + kq reduce ----
        float res[12];
#pragma unroll
        for (int r12 = 0; r12 < 12; r12++) {
            const ulonglong2* wr = reinterpret_cast<const ulonglong2*>(
                ws + (wid * 12 + r12) * HROW + kq * KSL);
            unsigned long long a0 = 0ULL, a1 = 0ULL;
#pragma unroll
            for (int i = 0; i < 10; i++) {
                ulonglong2 wv = wr[i];
                a0 = fma2(hPP[i].x, wv.x, a0);
                a1 = fma2(hPP[i].y, wv.y, a1);
            }
            float2 s0 = unpack2(a0), s1 = unpack2(a1);
            float a = (s0.x + s1.x) + (s0.y + s1.y);
            a += __shfl_xor_sync(0xffffffffu, a, 4);
            a += __shfl_xor_sync(0xffffffffu, a, 8);
            a += __shfl_xor_sync(0xffffffffu, a, 16);
            res[r12] = a;
        }

        // ---- gates + DSMEM broadcast of new h (producers: lanes 0-3) ----
        if (lane < 4 && valid_units) {
            float hn[4];
            const float* xr = &xr4.x; const float* xz = &xz4.x; const float* xn = &xn4.x;
            const float* br = &br4.x; const float* bz = &bz4.x; const float* bn = &bn4.x;
            const float* ho = &hold4.x;
#pragma unroll
            for (int j = 0; j < 4; j++) {
                float r = 1.0f / (1.0f + expf(-(xr[j] + res[3 * j + 0] + br[j])));
                float z = 1.0f / (1.0f + expf(-(xz[j] + res[3 * j + 1] + bz[j])));
                float n = tanhf(xn[j] + r * (res[3 * j + 2] + bn[j]));
                hn[j] = (1.0f - z) * n + z * ho[j];
            }
            // global output (consumed by the next GEMM)
            *reinterpret_cast<float4*>(
                out + ((long)tt * NB + bglob) * 600 + dir * 300 + gbase) =
                make_float4(hn[0], hn[1], hn[2], hn[3]);
            // push to all 8 peers' h_sm[nxt]
            unsigned long long lo = pack2(hn[0], hn[1]);
            unsigned long long hi = pack2(hn[2], hn[3]);
            uint32_t off = (uint32_t)((nxt * BPG + lb) * HROW + gbase) * 4u;
#pragma unroll
            for (int r = 0; r < CPC; r++) {
                uint32_t addr = peer_base[r] + off;
                st_cluster_b64(addr, lo);
                st_cluster_b64(addr + 8, hi);
            }
        }

        // ---- one cluster barrier per step (orders DSMEM stores) ----
        cluster_sync();
    }
}

// ---------------- span scoring: block per (i, b) ----------------
__global__ void span_kernel(const float* __restrict__ stt,
                            const float* __restrict__ endv,
                            float* __restrict__ fin,
                            const int* __restrict__ p_lens,
                            const float* __restrict__ w_a) {
    int i = blockIdx.x;   // 0..399
    int b = blockIdx.y;   // 0..31
    __shared__ float st[NF];
    __shared__ float wa[NF];
    int tid = threadIdx.x;
    for (int f = tid; f < NF; f += 128) {
        st[f] = stt[((long)i * NB + b) * NF + f];
        wa[f] = w_a[f];
    }
    __syncthreads();
    int wid = tid >> 5, lane = tid & 31;
    int plen = p_lens[b];
    for (int j = wid; j < NA; j += 4) {
        int k = i + j;
        float a = 0.0f;
        if (k < plen) {
            const float* ed = endv + ((long)k * NB + b) * NF;
#pragma unroll
            for (int cc = 0; cc < 10; cc++) {
                int f = lane + 32 * cc;
                if (f < NF) a += fmaxf(st[f] + ed[f], 0.0f) * wa[f];
            }
#pragma unroll
            for (int o = 16; o; o >>= 1) a += __shfl_xor_sync(0xffffffffu, a, o);
        }
        if (lane == 0) fin[(long)b * (T_P * NA) + i * NA + j] = (k < plen) ? a : 0.0f;
    }
}

// ---------------- log_softmax per batch row ----------------
__global__ void lsm_kernel(const float* __restrict__ fin, float* __restrict__ out) {
    int b = blockIdx.x;
    const float* src = fin + (long)b * (T_P * NA);
    float* dst = out + (long)b * (T_P * NA);
    __shared__ float red[256];
    int tid = threadIdx.x;
    float mx = -INFINITY;
    for (int n = tid; n < T_P * NA; n += 256) mx = fmaxf(mx, src[n]);
    red[tid] = mx; __syncthreads();
    for (int s = 128; s; s >>= 1) { if (tid < s) red[tid] = fmaxf(red[tid], red[tid + s]); __syncthreads(); }
    mx = red[0]; __syncthreads();
    float sum = 0.0f;
    for (int n = tid; n < T_P * NA; n += 256) sum += expf(src[n] - mx);
    red[tid] = sum; __syncthreads();
    for (int s = 128; s; s >>= 1) { if (tid < s) red[tid] += red[tid + s]; __syncthreads(); }
    float lse = mx + logf(red[0]);
    for (int n = tid; n < T_P * NA; n += 256) dst[n] = src[n] - lse;
}

// ---------------- driver ----------------
extern "C" void kernel_launch(void* const* d_in, const int* in_sizes, int n_in,
                              void* d_out, int out_size) {
    const int*   p        = (const int*)  d_in[0];
    const int*   q        = (const int*)  d_in[1];
    const float* p_mask   = (const float*)d_in[2];
    const float* q_mask   = (const float*)d_in[3];
    const int*   p_lens   = (const int*)  d_in[4];
    // d_in[5] = q_lens (unused by reference)
    const float* embed    = (const float*)d_in[6];
    const float* w_align  = (const float*)d_in[7];
    const float* b_align  = (const float*)d_in[8];
    const float* gru_w_ih = (const float*)d_in[9];
    const float* gru_w_hh = (const float*)d_in[10];
    const float* gru_b_ih = (const float*)d_in[11];
    const float* gru_b_hh = (const float*)d_in[12];
    const float* w_stt    = (const float*)d_in[13];
    const float* b_stt    = (const float*)d_in[14];
    const float* w_end    = (const float*)d_in[15];
    const float* b_end    = (const float*)d_in[16];
    const float* w_a      = (const float*)d_in[17];
    float* out = (float*)d_out;

    float* S = nullptr;
    cudaGetSymbolAddress((void**)&S, g_scratch);
    float* pstar = S + OFF_PSTAR;
    float* qemb  = S + OFF_QEMB;
    float* ffp   = S + OFF_FFP;
    float* ffq   = S + OFF_FFQ;
    float* xp    = S + OFF_XP;
    float* h1    = S + OFF_H1;
    float* h2    = S + OFF_H2;
    float* sttb  = S + OFF_STT;
    float* endb  = S + OFF_END;
    float* fin   = S + OFF_FIN;

    cudaFuncSetAttribute(gru_kernel, cudaFuncAttributeMaxDynamicSharedMemorySize,
                         GRU_SMEM_BYTES);

    dim3 blk(256);
    auto grid2 = [](int M, int N) { return dim3((N + BN - 1) / BN, (M + BM - 1) / BM); };

    // 1) gathers
    gather_kernel<<<(MP * NE + 255) / 256, 256>>>(p, embed, pstar, MP, 600);
    gather_kernel<<<(MQ * NE + 255) / 256, 256>>>(q, embed, qemb, MQ, 300);

    // 2) aligned-attention features
    sgemm_kernel<<<grid2(MP, NF), blk>>>(MP, NF, NE, pstar, 600, w_align, b_align, ffp, NF, 1);
    sgemm_kernel<<<grid2(MQ, NF), blk>>>(MQ, NF, NE, qemb, 300, w_align, b_align, ffq, NF, 1);

    // 3) attention softmax + q_align -> pstar[:,300:600]
    attn_kernel<<<(MP * 32 + 255) / 256, 256>>>(ffp, ffq, qemb, pstar, p_mask, q_mask);

    // 4) layer-0 input projections + recurrence
    for (int d = 0; d < 2; d++)
        sgemm_kernel<<<grid2(MP, 900), blk>>>(MP, 900, 600, pstar, 600,
                                              gru_w_ih + (long)d * 900 * 600,
                                              gru_b_ih + (long)d * 900,
                                              xp + (long)d * MP * 900, 900, 0);
    gru_kernel<<<128, GRU_THREADS, GRU_SMEM_BYTES>>>(gru_w_hh, gru_b_hh, xp, h1);

    // 5) layer-1
    for (int d = 0; d < 2; d++)
        sgemm_kernel<<<grid2(MP, 900), blk>>>(MP, 900, 600, h1, 600,
                                              gru_w_ih + (long)(2 + d) * 900 * 600,
                                              gru_b_ih + (long)(2 + d) * 900,
                                              xp + (long)d * MP * 900, 900, 0);
    gru_kernel<<<128, GRU_THREADS, GRU_SMEM_BYTES>>>(gru_w_hh + 2L * 900 * 300,
                                                     gru_b_hh + 2L * 900, xp, h2);

    // 6) start/end features
    sgemm_kernel<<<grid2(MP, NF), blk>>>(MP, NF, 600, h2, 600, w_stt, b_stt, sttb, NF, 1);
    sgemm_kernel<<<grid2(MP, NF), blk>>>(MP, NF, 600, h2, 600, w_end, b_end, endb, NF, 1);

    // 7) span scoring + masked log-softmax
    span_kernel<<<dim3(T_P, NB), 128>>>(sttb, endb, fin, p_lens, w_a);
    lsm_kernel<<<NB, 256>>>(fin, out);
}

// round 14
// speedup vs baseline: 1.2522x; 1.2522x over previous
#include <cuda_runtime.h>
#include <math.h>
#include <stdint.h>

// ---------------- problem constants ----------------
#define T_P 400
#define T_Q 30
#define NB  32
#define NE  300
#define NH  300
#define NF  300
#define NA  30
#define MP  (T_P*NB)   // 12800 rows (t*32+b)
#define MQ  (T_Q*NB)   // 960
#define HP  304        // padded k length for GRU (aligned float4)

// ---------------- scratch layout (floats) ----------------
#define OFF_PSTAR 0L                      // [MP][600]  (p_emb | q_align)
#define OFF_QEMB  7680000L                // [MQ][300]
#define OFF_FFP   7968000L                // [MP][300]
#define OFF_FFQ   11808000L               // [MQ][300]
#define OFF_XP    12096000L               // [MP][1800] (both dirs interleaved per row)
#define OFF_H1    35136000L               // [MP][600]
#define OFF_H2    42816000L               // [MP][600]
#define OFF_STT   50496000L               // [MP][300]
#define OFF_END   54336000L               // [MP][300]
#define OFF_FIN   58176000L               // [NB][12000]
#define SCRATCH_TOTAL 58560000L

__device__ float    g_scratch[SCRATCH_TOTAL];
__device__ float    g_H[2][2][NB][NH];    // [buf][dir][b][u] double-buffered hidden
__device__ unsigned g_bar[8 * 32];        // per-group counters, 128B apart

// ---------------- packed f32x2 helpers (FFMA2 path) ----------------
__device__ __forceinline__ unsigned long long fma2(unsigned long long a,
                                                   unsigned long long b,
                                                   unsigned long long c) {
    unsigned long long d;
    asm("fma.rn.f32x2 %0, %1, %2, %3;" : "=l"(d) : "l"(a), "l"(b), "l"(c));
    return d;
}
__device__ __forceinline__ unsigned long long pack2(float lo, float hi) {
    unsigned long long r;
    asm("mov.b64 %0, {%1, %2};" : "=l"(r) : "f"(lo), "f"(hi));
    return r;
}
__device__ __forceinline__ float2 unpack2(unsigned long long v) {
    float2 f;
    asm("mov.b64 {%0, %1}, %2;" : "=f"(f.x), "=f"(f.y) : "l"(v));
    return f;
}

// ---------------- reset (h state + barrier counters) ----------------
__global__ void reset_kernel() {
    int idx = blockIdx.x * blockDim.x + threadIdx.x;
    int tot = 2 * 2 * NB * NH;
    float* h = &g_H[0][0][0][0];
    for (int i = idx; i < tot; i += gridDim.x * blockDim.x) h[i] = 0.0f;
    if (idx < 8 * 32) g_bar[idx] = 0u;
}

// ---------------- embedding gather ----------------
__global__ void gather_kernel(const int* __restrict__ tok,
                              const float* __restrict__ embed,
                              float* __restrict__ dst, int rows, int dstride) {
    long idx = (long)blockIdx.x * blockDim.x + threadIdx.x;
    long tot = (long)rows * NE;
    if (idx >= tot) return;
    int m = (int)(idx / NE), e = (int)(idx % NE);
    dst[(long)m * dstride + e] = embed[(long)tok[m] * NE + e];
}

// ---------------- SGEMM (f32x2, BK=32): C[M,N] = A[M,K](lda) @ W[N,K]^T + bias ----------------
#define BM 128
#define BN 128
#define BK 32
__global__ __launch_bounds__(256, 2)
void sgemm_kernel(int M, int N, int K,
                  const float* __restrict__ A, int lda,
                  const float* __restrict__ W,
                  const float* __restrict__ bias,
                  float* __restrict__ C, int ldc, int do_relu) {
    __shared__ float As[BK][BM + 4];
    __shared__ float Bs[BK][BN + 4];
    int tid  = threadIdx.x;
    int trow = tid >> 4;          // 0..15 (M dir)
    int tcol = tid & 15;          // 0..15 (N dir)
    int aRow = tid >> 3;          // 0..31
    int aCol = tid & 7;           // 0..7 (float4 along K)
    int mBase = blockIdx.y * BM;
    int nBase = blockIdx.x * BN;

    unsigned long long accP[4][8];   // pairs over M: (2i, 2i+1) x 8 N
#pragma unroll
    for (int i = 0; i < 4; i++)
#pragma unroll
        for (int j = 0; j < 8; j++) accP[i][j] = 0ULL;

    for (int k0 = 0; k0 < K; k0 += BK) {
#pragma unroll
        for (int r = 0; r < 4; r++) {
            int m = mBase + aRow + r * 32;
            int k = k0 + aCol * 4;
            float4 v = make_float4(0.f, 0.f, 0.f, 0.f);
            if (m < M && k < K)
                v = *reinterpret_cast<const float4*>(A + (long)m * lda + k);
            As[aCol * 4 + 0][aRow + r * 32] = v.x;
            As[aCol * 4 + 1][aRow + r * 32] = v.y;
            As[aCol * 4 + 2][aRow + r * 32] = v.z;
            As[aCol * 4 + 3][aRow + r * 32] = v.w;
        }
#pragma unroll
        for (int r = 0; r < 4; r++) {
            int n = nBase + aRow + r * 32;
            int k = k0 + aCol * 4;
            float4 v = make_float4(0.f, 0.f, 0.f, 0.f);
            if (n < N && k < K)
                v = *reinterpret_cast<const float4*>(W + (long)n * K + k);
            Bs[aCol * 4 + 0][aRow + r * 32] = v.x;
            Bs[aCol * 4 + 1][aRow + r * 32] = v.y;
            Bs[aCol * 4 + 2][aRow + r * 32] = v.z;
            Bs[aCol * 4 + 3][aRow + r * 32] = v.w;
        }
        __syncthreads();
#pragma unroll
        for (int kk = 0; kk < BK; kk++) {
            ulonglong2 rm01 = *reinterpret_cast<const ulonglong2*>(&As[kk][trow * 8]);
            ulonglong2 rm23 = *reinterpret_cast<const ulonglong2*>(&As[kk][trow * 8 + 4]);
            float4 rnA = *reinterpret_cast<const float4*>(&Bs[kk][tcol * 8]);
            float4 rnB = *reinterpret_cast<const float4*>(&Bs[kk][tcol * 8 + 4]);
            unsigned long long rnD[8];
            rnD[0] = pack2(rnA.x, rnA.x); rnD[1] = pack2(rnA.y, rnA.y);
            rnD[2] = pack2(rnA.z, rnA.z); rnD[3] = pack2(rnA.w, rnA.w);
            rnD[4] = pack2(rnB.x, rnB.x); rnD[5] = pack2(rnB.y, rnB.y);
            rnD[6] = pack2(rnB.z, rnB.z); rnD[7] = pack2(rnB.w, rnB.w);
            unsigned long long rmP[4] = { rm01.x, rm01.y, rm23.x, rm23.y };
#pragma unroll
            for (int i = 0; i < 4; i++)
#pragma unroll
                for (int j = 0; j < 8; j++)
                    accP[i][j] = fma2(rmP[i], rnD[j], accP[i][j]);
        }
        __syncthreads();
    }
#pragma unroll
    for (int i2 = 0; i2 < 4; i2++) {
#pragma unroll
        for (int j = 0; j < 8; j++) {
            int n = nBase + tcol * 8 + j;
            if (n >= N) continue;
            float2 v2 = unpack2(accP[i2][j]);
            float bsv = bias[n];
            int m0 = mBase + trow * 8 + 2 * i2;
            float v = v2.x + bsv;
            if (do_relu) v = fmaxf(v, 0.0f);
            if (m0 < M) C[(long)m0 * ldc + n] = v;
            v = v2.y + bsv;
            if (do_relu) v = fmaxf(v, 0.0f);
            if (m0 + 1 < M) C[(long)(m0 + 1) * ldc + n] = v;
        }
    }
}

// ---------------- attention: scores -> softmax -> q_align (warp per (p,b)) ----------------
__global__ void attn_kernel(const float* __restrict__ ffp,
                            const float* __restrict__ ffq,
                            const float* __restrict__ qemb,
                            float* __restrict__ pstar,
                            const float* __restrict__ pmask,
                            const float* __restrict__ qmask) {
    int gw = (blockIdx.x * blockDim.x + threadIdx.x) >> 5;
    int lane = threadIdx.x & 31;
    if (gw >= MP) return;
    int b = gw & 31;
    int m = gw;

    float fp[10];
#pragma unroll
    for (int c = 0; c < 10; c++) {
        int f = lane + 32 * c;
        fp[c] = (f < NF) ? ffp[(long)m * NF + f] : 0.0f;
    }
    float pm = pmask[m];

    float myscore = 0.0f;
    for (int q = 0; q < T_Q; q++) {
        const float* fq = ffq + (long)(q * NB + b) * NF;
        float a = 0.0f;
#pragma unroll
        for (int c = 0; c < 10; c++) {
            int f = lane + 32 * c;
            if (f < NF) a += fp[c] * fq[f];
        }
#pragma unroll
        for (int o = 16; o; o >>= 1) a += __shfl_xor_sync(0xffffffffu, a, o);
        float s = a * pm * qmask[q * NB + b];
        if (lane == q) myscore = s;
    }
    float val = (lane < T_Q) ? myscore : -INFINITY;
    float mx = val;
#pragma unroll
    for (int o = 16; o; o >>= 1) mx = fmaxf(mx, __shfl_xor_sync(0xffffffffu, mx, o));
    float e = (lane < T_Q) ? expf(val - mx) : 0.0f;
    float sum = e;
#pragma unroll
    for (int o = 16; o; o >>= 1) sum += __shfl_xor_sync(0xffffffffu, sum, o);
    float w = e / sum;

    float acc[10];
#pragma unroll
    for (int c = 0; c < 10; c++) acc[c] = 0.0f;
    for (int q = 0; q < T_Q; q++) {
        float wq = __shfl_sync(0xffffffffu, w, q);
        const float* qe = qemb + (long)(q * NB + b) * NE;
#pragma unroll
        for (int c = 0; c < 10; c++) {
            int f = lane + 32 * c;
            if (f < NE) acc[c] += wq * qe[f];
        }
    }
#pragma unroll
    for (int c = 0; c < 10; c++) {
        int f = lane + 32 * c;
        if (f < NE) pstar[(long)m * 600 + 300 + f] = acc[c];
    }
}

// ---------------- persistent bi-GRU layer (round-10 base + overlap tweaks) ----------------
// 120 CTAs: 8 groups = (dir) x (bgroup of 8 batches), 15 CTAs/group, 20 units/CTA.
// 320 threads = 10 warps; warp w owns 2 complete units (all 3 gates = 6 rows).
// Lanes: lb = lane&7 -> batch, kq = lane>>3 -> 76-wide padded k-quarter.
// Exchange path: stcg float2 h stores -> sync -> arrive -> NEXT-STEP xp prefetch
// (overlaps DRAM latency with the poll) -> poll -> sync -> coalesced h restage.
__global__ __launch_bounds__(320)
void gru_kernel(const float* __restrict__ whh,     // [2][900][300] for this layer
                const float* __restrict__ bhh,     // [2][900]
                const float* __restrict__ xp_all,  // [MP][1800] (x@Wih^T + b_ih, dirs side by side)
                float* __restrict__ out) {         // [MP][600]
    extern __shared__ float sm[];
    float* ws   = sm;              // [60][HP] row rr = ul*3 + gate
    float* h_sm = sm + 60 * HP;    // [8][HP]

    int bx  = blockIdx.x;
    int grp = bx / 15, c = bx % 15;
    int dir = grp >> 2, bg = grp & 3;
    int u0  = c * 20;
    int tid = threadIdx.x;
    int wid = tid >> 5, lane = tid & 31;
    int lb = lane & 7, kq = lane >> 3;

    // stage this CTA's 60 weight rows (unit-major, gate-minor), zero-padded
    const float* wbase = whh + (long)dir * 900 * 300;
    for (int e = tid; e < 60 * HP; e += 320) {
        int rr = e / HP, k = e % HP;
        int ul = rr / 3, gate = rr % 3;
        int grow = gate * 300 + u0 + ul;
        ws[e] = (k < 300) ? wbase[(long)grow * 300 + k] : 0.0f;
    }
    // zero h_sm pad columns once
    for (int e = tid; e < 8 * HP; e += 320) {
        if ((e % HP) >= 300) h_sm[e] = 0.0f;
    }

    int ua = u0 + 2 * wid;
    int ub = ua + 1;
    int bglob = bg * 8 + lb;
    const float* bh = bhh + (long)dir * 900;
    float bra = bh[ua], bza = bh[300 + ua], bna = bh[600 + ua];
    float brb = bh[ub], bzb = bh[300 + ub], bnb = bh[600 + ub];

    unsigned* bar = &g_bar[grp * 32];
    const float4* hsrc0 = reinterpret_cast<const float4*>(&g_H[0][dir][bg * 8][0]);
    const float4* hsrc1 = reinterpret_cast<const float4*>(&g_H[1][dir][bg * 8][0]);
    __syncthreads();

    // prefetch step-0 xp gate inputs
    float xpv[6];
    if (kq == 0) {
        int tt0 = dir ? (T_P - 1) : 0;
        const float* xp = xp_all + ((long)tt0 * NB + bglob) * 1800 + dir * 900;
        xpv[0] = xp[ua]; xpv[1] = xp[300 + ua]; xpv[2] = xp[600 + ua];
        xpv[3] = xp[ub]; xpv[4] = xp[300 + ub]; xpv[5] = xp[600 + ub];
    }

    for (int step = 0; step < T_P; step++) {
        int cur = step & 1;
        int tt  = dir ? (T_P - 1 - step) : step;

        // ---- stage h (8x300) coalesced from L2 into padded smem ----
        {
            const float4* hsrc = cur ? hsrc1 : hsrc0;
            for (int e = tid; e < 600; e += 320) {
                float4 v = __ldcg(hsrc + e);
                int row = e / 75, col = e - row * 75;   // 75 float4 per 300-float row
                *reinterpret_cast<float4*>(h_sm + row * HP + col * 4) = v;
            }
        }
        __syncthreads();

        // ---- load my padded h slice as f32x2 pairs (19 x LDS.128) ----
        ulonglong2 hPP[19];
        {
            const ulonglong2* hrow =
                reinterpret_cast<const ulonglong2*>(h_sm + lb * HP + kq * 76);
#pragma unroll
            for (int i = 0; i < 19; i++) hPP[i] = hrow[i];
        }

        // ---- dot: 6 rows (2 units x 3 gates), f32x2 dual-chain ----
        float res[6];
#pragma unroll
        for (int r6 = 0; r6 < 6; r6++) {
            int rr = wid * 6 + r6;
            const ulonglong2* wr =
                reinterpret_cast<const ulonglong2*>(ws + rr * HP + kq * 76);
            unsigned long long a0 = 0ULL, a1 = 0ULL;
#pragma unroll
            for (int i = 0; i < 19; i++) {
                ulonglong2 wv = wr[i];
                a0 = fma2(hPP[i].x, wv.x, a0);
                a1 = fma2(hPP[i].y, wv.y, a1);
            }
            float2 s0 = unpack2(a0), s1 = unpack2(a1);
            float a = (s0.x + s1.x) + (s0.y + s1.y);
            a += __shfl_xor_sync(0xffffffffu, a, 8);
            a += __shfl_xor_sync(0xffffffffu, a, 16);
            res[r6] = a;
        }

        // ---- gates in-warp (lanes kq==0: one lane per batch), float2 stores ----
        if (kq == 0) {
            float r = 1.0f / (1.0f + expf(-(xpv[0] + res[0] + bra)));
            float z = 1.0f / (1.0f + expf(-(xpv[1] + res[1] + bza)));
            float n = tanhf(xpv[2] + r * (res[2] + bna));
            float hna = (1.0f - z) * n + z * h_sm[lb * HP + ua];
            r = 1.0f / (1.0f + expf(-(xpv[3] + res[3] + brb)));
            z = 1.0f / (1.0f + expf(-(xpv[4] + res[4] + bzb)));
            n = tanhf(xpv[5] + r * (res[5] + bnb));
            float hnb = (1.0f - z) * n + z * h_sm[lb * HP + ub];
            float2 hv = make_float2(hna, hnb);
            __stcg(reinterpret_cast<float2*>(&g_H[cur ^ 1][dir][bglob][ua]), hv);
            *reinterpret_cast<float2*>(
                out + ((long)tt * NB + bglob) * 600 + dir * 300 + ua) = hv;
        }
        __syncthreads();
        if (step == T_P - 1) break;   // no barrier needed after last step

        // ---- arrive, then overlap next-step xp prefetch with the poll ----
        if (tid == 0) {
            __threadfence();
            atomicAdd(bar, 1u);
        }
        if (kq == 0) {
            int tt2 = dir ? (T_P - 2 - step) : (step + 1);
            const float* xp = xp_all + ((long)tt2 * NB + bglob) * 1800 + dir * 900;
            xpv[0] = xp[ua]; xpv[1] = xp[300 + ua]; xpv[2] = xp[600 + ua];
            xpv[3] = xp[ub]; xpv[4] = xp[300 + ub]; xpv[5] = xp[600 + ub];
        }
        if (tid == 0) {
            unsigned target = (unsigned)(step + 1) * 15u;
            unsigned v;
            while (true) {
                asm volatile("ld.global.cg.u32 %0, [%1];" : "=r"(v) : "l"(bar) : "memory");
                if (v >= target) break;
                __nanosleep(16);
            }
            __threadfence();
        }
        __syncthreads();
    }
}

// ---------------- span scoring: block per (i, b) ----------------
__global__ void span_kernel(const float* __restrict__ stt,
                            const float* __restrict__ endv,
                            float* __restrict__ fin,
                            const int* __restrict__ p_lens,
                            const float* __restrict__ w_a) {
    int i = blockIdx.x;   // 0..399
    int b = blockIdx.y;   // 0..31
    __shared__ float st[NF];
    __shared__ float wa[NF];
    int tid = threadIdx.x;
    for (int f = tid; f < NF; f += 128) {
        st[f] = stt[((long)i * NB + b) * NF + f];
        wa[f] = w_a[f];
    }
    __syncthreads();
    int wid = tid >> 5, lane = tid & 31;
    int plen = p_lens[b];
    for (int j = wid; j < NA; j += 4) {
        int k = i + j;
        float a = 0.0f;
        if (k < plen) {
            const float* ed = endv + ((long)k * NB + b) * NF;
#pragma unroll
            for (int cc = 0; cc < 10; cc++) {
                int f = lane + 32 * cc;
                if (f < NF) a += fmaxf(st[f] + ed[f], 0.0f) * wa[f];
            }
#pragma unroll
            for (int o = 16; o; o >>= 1) a += __shfl_xor_sync(0xffffffffu, a, o);
        }
        if (lane == 0) fin[(long)b * (T_P * NA) + i * NA + j] = (k < plen) ? a : 0.0f;
    }
}

// ---------------- log_softmax per batch row ----------------
__global__ void lsm_kernel(const float* __restrict__ fin, float* __restrict__ out) {
    int b = blockIdx.x;
    const float* src = fin + (long)b * (T_P * NA);
    float* dst = out + (long)b * (T_P * NA);
    __shared__ float red[256];
    int tid = threadIdx.x;
    float mx = -INFINITY;
    for (int n = tid; n < T_P * NA; n += 256) mx = fmaxf(mx, src[n]);
    red[tid] = mx; __syncthreads();
    for (int s = 128; s; s >>= 1) { if (tid < s) red[tid] = fmaxf(red[tid], red[tid + s]); __syncthreads(); }
    mx = red[0]; __syncthreads();
    float sum = 0.0f;
    for (int n = tid; n < T_P * NA; n += 256) sum += expf(src[n] - mx);
    red[tid] = sum; __syncthreads();
    for (int s = 128; s; s >>= 1) { if (tid < s) red[tid] += red[tid + s]; __syncthreads(); }
    float lse = mx + logf(red[0]);
    for (int n = tid; n < T_P * NA; n += 256) dst[n] = src[n] - lse;
}

// ---------------- driver ----------------
extern "C" void kernel_launch(void* const* d_in, const int* in_sizes, int n_in,
                              void* d_out, int out_size) {
    const int*   p        = (const int*)  d_in[0];
    const int*   q        = (const int*)  d_in[1];
    const float* p_mask   = (const float*)d_in[2];
    const float* q_mask   = (const float*)d_in[3];
    const int*   p_lens   = (const int*)  d_in[4];
    // d_in[5] = q_lens (unused by reference)
    const float* embed    = (const float*)d_in[6];
    const float* w_align  = (const float*)d_in[7];
    const float* b_align  = (const float*)d_in[8];
    const float* gru_w_ih = (const float*)d_in[9];
    const float* gru_w_hh = (const float*)d_in[10];
    const float* gru_b_ih = (const float*)d_in[11];
    const float* gru_b_hh = (const float*)d_in[12];
    const float* w_stt    = (const float*)d_in[13];
    const float* b_stt    = (const float*)d_in[14];
    const float* w_end    = (const float*)d_in[15];
    const float* b_end    = (const float*)d_in[16];
    const float* w_a      = (const float*)d_in[17];
    float* out = (float*)d_out;

    float* S = nullptr;
    cudaGetSymbolAddress((void**)&S, g_scratch);
    float* pstar = S + OFF_PSTAR;
    float* qemb  = S + OFF_QEMB;
    float* ffp   = S + OFF_FFP;
    float* ffq   = S + OFF_FFQ;
    float* xp    = S + OFF_XP;
    float* h1    = S + OFF_H1;
    float* h2    = S + OFF_H2;
    float* sttb  = S + OFF_STT;
    float* endb  = S + OFF_END;
    float* fin   = S + OFF_FIN;

    const int GRU_SMEM = (60 * HP + 8 * HP) * 4;   // 82688 B
    cudaFuncSetAttribute(gru_kernel, cudaFuncAttributeMaxDynamicSharedMemorySize, GRU_SMEM);

    dim3 blk(256);
    auto grid2 = [](int M, int N) { return dim3((N + BN - 1) / BN, (M + BM - 1) / BM); };

    // 1) reset + gathers
    reset_kernel<<<64, 256>>>();
    gather_kernel<<<(MP * NE + 255) / 256, 256>>>(p, embed, pstar, MP, 600);
    gather_kernel<<<(MQ * NE + 255) / 256, 256>>>(q, embed, qemb, MQ, 300);

    // 2) aligned-attention features
    sgemm_kernel<<<grid2(MP, NF), blk>>>(MP, NF, NE, pstar, 600, w_align, b_align, ffp, NF, 1);
    sgemm_kernel<<<grid2(MQ, NF), blk>>>(MQ, NF, NE, qemb, 300, w_align, b_align, ffq, NF, 1);

    // 3) attention softmax + q_align -> pstar[:,300:600]
    attn_kernel<<<(MP * 32 + 255) / 256, 256>>>(ffp, ffq, qemb, pstar, p_mask, q_mask);

    // 4) layer-0 input projections (both dirs in ONE GEMM, N=1800) + recurrence
    sgemm_kernel<<<grid2(MP, 1800), blk>>>(MP, 1800, 600, pstar, 600,
                                           gru_w_ih, gru_b_ih, xp, 1800, 0);
    gru_kernel<<<120, 320, GRU_SMEM>>>(gru_w_hh, gru_b_hh, xp, h1);

    // 5) layer-1
    reset_kernel<<<64, 256>>>();
    sgemm_kernel<<<grid2(MP, 1800), blk>>>(MP, 1800, 600, h1, 600,
                                           gru_w_ih + 2L * 900 * 600,
                                           gru_b_ih + 1800, xp, 1800, 0);
    gru_kernel<<<120, 320, GRU_SMEM>>>(gru_w_hh + 2L * 900 * 300,
                                       gru_b_hh + 1800, xp, h2);

    // 6) start/end features
    sgemm_kernel<<<grid2(MP, NF), blk>>>(MP, NF, 600, h2, 600, w_stt, b_stt, sttb, NF, 1);
    sgemm_kernel<<<grid2(MP, NF), blk>>>(MP, NF, 600, h2, 600, w_end, b_end, endb, NF, 1);

    // 7) span scoring + masked log-softmax
    span_kernel<<<dim3(T_P, NB), 128>>>(sttb, endb, fin, p_lens, w_a);
    lsm_kernel<<<NB, 256>>>(fin, out);
}